// round 15
// baseline (speedup 1.0000x reference)
#include <cuda_runtime.h>
#include <math.h>

// Problem constants
#define NN     512
#define HID    1024
#define OUTD   131328          // N + N*(N-1)/2
#define OUT4   (OUTD / 4)      // 32832 float4 columns
#define SPLITK 8
#define JCH    (HID / SPLITK)  // 128 rows of Wo per k-chunk
#define SI     16              // i-splits in MLP head (32 colgroups x 16)
#define FB     1032            // blocks in fused head kernel (129 x 8)
#define MLPB   512             // blocks running the MLP inside the head
#define GT     136             // lower-triangle 32x32 tiles (16*17/2)
#define PFN    40              // Wo rows staged per waiter column (85MB total)

// Device scratch (no allocation allowed). Referenced ONLY in device code.
__device__ float g_hp[3][SI][HID];       // MLP split-i partials (pre-bias/tanh)
__device__ float g_part[SPLITK][OUTD];   // split-K partial sums of big GEMV
__device__ float g_L[NN * NN];
__device__ float g_sink;                 // never-written dummy (defeats DCE)

// ---------------------------------------------------------------------------
// Two independent sense-reversal grid barriers:
//   counter 1: all FB blocks (head kernel) and GT blocks (tail kernel)
//   counter 2: the MLPB MLP blocks only
// Safe: FB=1032 <= 148*7 co-resident at 256thr/36regs; MLPB,GT <= 148.
// ---------------------------------------------------------------------------
__device__ unsigned g_bar_ctr = 0;
__device__ volatile unsigned g_bar_gen = 0;
__device__ unsigned g_bar2_ctr = 0;
__device__ volatile unsigned g_bar2_gen = 0;

__device__ __forceinline__ void barrier_impl(unsigned nblocks,
                                             unsigned* ctr,
                                             volatile unsigned* gen_p) {
    __threadfence();
    __syncthreads();
    if (threadIdx.x == 0) {
        unsigned gen = *gen_p;
        if (atomicAdd(ctr, 1) == nblocks - 1) {
            *ctr = 0;
            __threadfence();
            *gen_p = gen + 1;
        } else {
            while (*gen_p == gen) __nanosleep(32);
        }
        __threadfence();
    }
    __syncthreads();
}

__device__ __forceinline__ void barrier_all(unsigned n)  { barrier_impl(n, &g_bar_ctr,  &g_bar_gen);  }
__device__ __forceinline__ void barrier_mlp(unsigned n)  { barrier_impl(n, &g_bar2_ctr, &g_bar2_gen); }

// ---------------------------------------------------------------------------
// MLP partial (round-10 proven core). Warp lanes -> 32 consecutive columns.
// ---------------------------------------------------------------------------
template <int IN>
__device__ __forceinline__ void mlp_partial(
    const float* __restrict__ xs, const float* __restrict__ W,
    int cg, int isp, float* __restrict__ outp, float sh[8][32]) {
    const int CHUNK = IN / SI;
    const int CH    = CHUNK / 8;
    const int lane  = threadIdx.x & 31;
    const int w     = threadIdx.x >> 5;
    const int j     = cg * 32 + lane;
    const int base  = isp * CHUNK;
    const int i0    = w * CH;

    float acc = 0.f;
#pragma unroll
    for (int i = 0; i < CH; ++i) {
        acc += xs[i0 + i] * __ldg(&W[(size_t)(base + i0 + i) * 1024 + j]);
    }
    sh[w][lane] = acc;
    __syncthreads();
    if (w == 0) {
        float s = 0.f;
#pragma unroll
        for (int q = 0; q < 8; ++q) s += sh[q][lane];
        outp[j] = s;
    }
    __syncthreads();
}

// ---------------------------------------------------------------------------
// Fused head: MLP (blocks 0..511) || Wo L2-staging (blocks 512..1031),
// one full-grid barrier, then the proven split-K gemv on all 1032 blocks.
// ---------------------------------------------------------------------------
__global__ void __launch_bounds__(256, 7)
head_kernel(const float* __restrict__ x,
            const float* __restrict__ W0, const float* __restrict__ b0,
            const float* __restrict__ W1, const float* __restrict__ b1,
            const float* __restrict__ W2, const float* __restrict__ b2,
            const float* __restrict__ Wo) {
    __shared__ float sh[8][32];
    __shared__ float xs[HID / SI];
    __shared__ float hs[JCH];

    const int b = blockIdx.x;
    const int t = threadIdx.x;

    // gemv assignment (used by staging and by the gemv phase)
    const int chunk = b & 7;
    const int kb    = b >> 3;
    const int k4    = kb * 256 + t;

    if (b < MLPB) {
        // ================= MLP half =================
        const int cg  = b & 31;
        const int isp = b >> 5;

        {   // layer 0: IN=512
            const int CHUNK = 512 / SI;
            for (int i = t; i < CHUNK; i += 256) xs[i] = x[isp * CHUNK + i];
            __syncthreads();
            mlp_partial<512>(xs, W0, cg, isp, g_hp[0][isp], sh);
        }
        barrier_mlp(MLPB);

        {   // layer 1: IN=1024
            const int CHUNK = HID / SI;
            for (int i = t; i < CHUNK; i += 256) {
                const int g = isp * CHUNK + i;
                float s = __ldg(&b0[g]);
#pragma unroll
                for (int q = 0; q < SI; ++q) s += g_hp[0][q][g];
                xs[i] = tanhf(s);
            }
            __syncthreads();
            mlp_partial<1024>(xs, W1, cg, isp, g_hp[1][isp], sh);
        }
        barrier_mlp(MLPB);

        {   // layer 2: IN=1024
            const int CHUNK = HID / SI;
            for (int i = t; i < CHUNK; i += 256) {
                const int g = isp * CHUNK + i;
                float s = __ldg(&b1[g]);
#pragma unroll
                for (int q = 0; q < SI; ++q) s += g_hp[1][q][g];
                xs[i] = tanhf(s);
            }
            __syncthreads();
            mlp_partial<1024>(xs, W2, cg, isp, g_hp[2][isp], sh);
        }
    } else {
        // ============ staging half: pull own column head into L2 ============
        // Real LDG (not droppable), evict-normal -> resident for gemv phase.
        if (k4 < OUT4) {
            const float4* W4 = (const float4*)Wo + (size_t)chunk * JCH * OUT4;
            float acc = 0.f;
#pragma unroll 8
            for (int j = 0; j < PFN; ++j) {
                float4 v = __ldg(&W4[(size_t)j * OUT4 + k4]);
                acc += v.x + v.y + v.z + v.w;
            }
            if (acc == 1.2345e37f) g_sink = acc;   // never true; defeats DCE
        }
    }

    barrier_all(FB);

    // ================= gemv phase (proven core) =================
    if (t < JCH) {
        const int g = chunk * JCH + t;
        float s = __ldg(&b2[g]);
#pragma unroll
        for (int q = 0; q < SI; ++q) s += g_hp[2][q][g];
        hs[t] = tanhf(s);
    }
    __syncthreads();

    if (k4 < OUT4) {
        const float4* W4 = (const float4*)Wo + (size_t)chunk * JCH * OUT4;
        float ax = 0.f, ay = 0.f, az = 0.f, aw = 0.f;
#pragma unroll 8
        for (int j = 0; j < JCH; ++j) {
            float4 wv = __ldcs(&W4[(size_t)j * OUT4 + k4]);
            float  hj = hs[j];
            ax += hj * wv.x;
            ay += hj * wv.y;
            az += hj * wv.z;
            aw += hj * wv.w;
        }
        float4 r; r.x = ax; r.y = ay; r.z = az; r.w = aw;
        ((float4*)g_part[chunk])[k4] = r;
    }
}

// ---------------------------------------------------------------------------
// Fused build_L + D = L*L^T (round-12 proven, 512 threads).
// ---------------------------------------------------------------------------
__global__ void __launch_bounds__(512)
buildL_gemm(const float* __restrict__ bo, float* __restrict__ D) {
    __shared__ float SAB[2][64][36];   // As/Bs; reduction buffer overlaid

    const int b = blockIdx.x;
    const int t = threadIdx.x;         // 0..511

    // linear block id -> (bi, bj), bj <= bi
    int bi = (int)((sqrtf(8.f * b + 1.f) - 1.f) * 0.5f);
    while ((bi + 1) * (bi + 2) / 2 <= b) ++bi;
    while (bi * (bi + 1) / 2 > b) --bi;
    const int bj = b - bi * (bi + 1) / 2;

    // ---- Phase A: build L ----
    {
        const int T = GT * 512;
        for (int idx = b * 512 + t; idx < NN * NN; idx += T) {
            const int r = idx >> 9;
            const int c = idx & 511;
            float v;
            if (c > r) {
                v = 0.f;
            } else {
                const int k = (c < r) ? (NN + (r * (r - 1)) / 2 + c) : r;
                float s = __ldg(&bo[k]);
#pragma unroll
                for (int q = 0; q < SPLITK; ++q) s += g_part[q][k];
                v = (c < r) ? s : expf(s);
            }
            g_L[idx] = v;
        }
    }
    barrier_all(GT);

    // ---- Phase B: GEMM ----
    float (*As)[36] = SAB[0];
    float (*Bs)[36] = SAB[1];

    const int grp  = t >> 6;              // 0..7: k-groups of 8
    const int id64 = t & 63;
    const int tx   = id64 & 7;
    const int ty   = id64 >> 3;

    const int lr = t >> 4;                // 0..31
    const int lc = (t & 15) * 4;          // 0,4,...,60

    float acc[4][4];
#pragma unroll
    for (int i = 0; i < 4; ++i)
#pragma unroll
        for (int j = 0; j < 4; ++j) acc[i][j] = 0.f;

    const int nslab = (bj >> 1) + 1;      // L triangular: k <= bj*32+31

    for (int s = 0; s < nslab; ++s) {
        const int k0 = s * 64;
        float4 av = *(const float4*)&g_L[(size_t)(bi * 32 + lr) * NN + k0 + lc];
        float4 bv = *(const float4*)&g_L[(size_t)(bj * 32 + lr) * NN + k0 + lc];
        As[lc][lr] = av.x; As[lc + 1][lr] = av.y; As[lc + 2][lr] = av.z; As[lc + 3][lr] = av.w;
        Bs[lc][lr] = bv.x; Bs[lc + 1][lr] = bv.y; Bs[lc + 2][lr] = bv.z; Bs[lc + 3][lr] = bv.w;
        __syncthreads();

        const int kb = grp * 8;
#pragma unroll
        for (int kk = 0; kk < 8; ++kk) {
            float4 a  = *(const float4*)&As[kb + kk][ty * 4];
            float4 bb = *(const float4*)&Bs[kb + kk][tx * 4];
            acc[0][0] += a.x * bb.x; acc[0][1] += a.x * bb.y; acc[0][2] += a.x * bb.z; acc[0][3] += a.x * bb.w;
            acc[1][0] += a.y * bb.x; acc[1][1] += a.y * bb.y; acc[1][2] += a.y * bb.z; acc[1][3] += a.y * bb.w;
            acc[2][0] += a.z * bb.x; acc[2][1] += a.z * bb.y; acc[2][2] += a.z * bb.z; acc[2][3] += a.z * bb.w;
            acc[3][0] += a.w * bb.x; acc[3][1] += a.w * bb.y; acc[3][2] += a.w * bb.z; acc[3][3] += a.w * bb.w;
        }
        __syncthreads();
    }

    // two-stage 8-group reduction (overlay on SAB)
    float* red = &SAB[0][0][0];
    if (grp >= 4) {
        float* dst = red + ((grp - 4) * 64 + id64) * 16;
#pragma unroll
        for (int i = 0; i < 4; ++i)
#pragma unroll
            for (int j = 0; j < 4; ++j) dst[i * 4 + j] = acc[i][j];
    }
    __syncthreads();
    if (grp < 4) {
        const float* src = red + (grp * 64 + id64) * 16;
#pragma unroll
        for (int i = 0; i < 4; ++i)
#pragma unroll
            for (int j = 0; j < 4; ++j) acc[i][j] += src[i * 4 + j];
    }
    __syncthreads();
    if (grp >= 1 && grp < 4) {
        float* dst = red + ((grp - 1) * 64 + id64) * 16;
#pragma unroll
        for (int i = 0; i < 4; ++i)
#pragma unroll
            for (int j = 0; j < 4; ++j) dst[i * 4 + j] = acc[i][j];
    }
    __syncthreads();
    if (grp == 0) {
#pragma unroll
        for (int g = 0; g < 3; ++g) {
            const float* src = red + (g * 64 + id64) * 16;
#pragma unroll
            for (int i = 0; i < 4; ++i)
#pragma unroll
                for (int j = 0; j < 4; ++j) acc[i][j] += src[i * 4 + j];
        }

        const int R = bi * 32 + ty * 4;
        const int C = bj * 32 + tx * 4;
#pragma unroll
        for (int i = 0; i < 4; ++i) {
            float4 v; v.x = acc[i][0]; v.y = acc[i][1]; v.z = acc[i][2]; v.w = acc[i][3];
            *(float4*)&D[(size_t)(R + i) * NN + C] = v;
        }
        if (bi != bj) {   // mirror (D symmetric)
#pragma unroll
            for (int j = 0; j < 4; ++j) {
                float4 v; v.x = acc[0][j]; v.y = acc[1][j]; v.z = acc[2][j]; v.w = acc[3][j];
                *(float4*)&D[(size_t)(C + j) * NN + R] = v;
            }
        }
    }
}

// ---------------------------------------------------------------------------
extern "C" void kernel_launch(void* const* d_in, const int* in_sizes, int n_in,
                              void* d_out, int out_size) {
    const float* input = (const float*)d_in[0];
    const float* W0    = (const float*)d_in[1];
    const float* b0    = (const float*)d_in[2];
    const float* W1    = (const float*)d_in[3];
    const float* b1    = (const float*)d_in[4];
    const float* W2    = (const float*)d_in[5];
    const float* b2    = (const float*)d_in[6];
    const float* Wo    = (const float*)d_in[7];
    const float* bo    = (const float*)d_in[8];
    float* out = (float*)d_out;

    // MLP || Wo L2-staging, one grid barrier, then the 537MB gemv
    head_kernel<<<FB, 256>>>(input, W0, b0, W1, b1, W2, b2, Wo);

    // Fused L assembly + D = L L^T
    buildL_gemm<<<GT, 512>>>(bo, out);
}